// round 11
// baseline (speedup 1.0000x reference)
#include <cuda_runtime.h>
#include <cstdint>
#include <cfloat>

#define INSZ   128
#define OUTSZ  128
#define BATCH  1024
#define NCHUNK 8
#define BC     128
#define TSTRIDE 148   // smem floats per i-row (16B-aligned, odd/32-friendly banks)

typedef unsigned long long u64;

__device__ __forceinline__ u64 pk(float a, float b) {
    u64 r; asm("mov.b64 %0, {%1, %2};" : "=l"(r) : "f"(a), "f"(b)); return r;
}
__device__ __forceinline__ void upk(u64 v, float& a, float& b) {
    asm("mov.b64 {%0, %1}, %2;" : "=f"(a), "=f"(b) : "l"(v));
}
__device__ __forceinline__ u64 ffma2(u64 a, u64 b, u64 c) {
    u64 d; asm("fma.rn.f32x2 %0, %1, %2, %3;" : "=l"(d) : "l"(a), "l"(b), "l"(c)); return d;
}
__device__ __forceinline__ u64 fmul2(u64 a, u64 b) {
    u64 d; asm("mul.rn.f32x2 %0, %1, %2;" : "=l"(d) : "l"(a), "l"(b)); return d;
}
__device__ __forceinline__ u64 fadd2(u64 a, u64 b) {
    u64 d; asm("add.rn.f32x2 %0, %1, %2;" : "=l"(d) : "l"(a), "l"(b)); return d;
}

// Precomputed piecewise-affine layer-2 tables.
// g_tab[o][i][r][0..7]=A_j[r], [8..15]=B_j[r];  g_kn[o][i][0..7]=sorted knees.
__device__ float g_tab[(size_t)OUTSZ * INSZ * 144];
__device__ float g_kn [(size_t)OUTSZ * INSZ * 8];

// ---------------------------------------------------------------------------
// Precompute: per subnet (i,o), the 8 layer-1 knees v_k = -c_k/a_k and, for
// each of the 9 regions between sorted knees, the affine coefficients of the
// layer-2 pre-activations:  g_j(v) = A_j[r]*v + B_j[r].
// Exact algebra (region active-sets), so eval matches the direct network.
// ---------------------------------------------------------------------------
__global__ void precompute_kernel(const float* __restrict__ W1, const float* __restrict__ b1,
                                  const float* __restrict__ W2, const float* __restrict__ b2) {
    const int o = blockIdx.x;
    const int i = threadIdx.x;
    const int n = i * OUTSZ + o;

    float a[8], c[8];
#pragma unroll
    for (int k = 0; k < 8; k++) { a[k] = W1[(size_t)n * 8 + k]; c[k] = b1[(size_t)n * 8 + k]; }
    float w2[64];
#pragma unroll
    for (int e = 0; e < 64; e++) w2[e] = W2[(size_t)n * 64 + e];
    float b2v[8];
#pragma unroll
    for (int j = 0; j < 8; j++) b2v[j] = b2[(size_t)n * 8 + j];

    // knees (a==0 -> sentinel at -FLT_MAX: always below any v; handled as const)
    float knee[8];
#pragma unroll
    for (int k = 0; k < 8; k++)
        knee[k] = (a[k] != 0.0f) ? (-c[k] / a[k]) : -FLT_MAX;

    // rank[k] = #knees strictly less (ties broken by index) -> a permutation
    int rank[8];
#pragma unroll
    for (int k = 0; k < 8; k++) {
        int rk = 0;
#pragma unroll
        for (int m = 0; m < 8; m++)
            rk += (knee[m] < knee[k]) || (knee[m] == knee[k] && m < k);
        rank[k] = rk;
    }

    // sorted knees to gmem (scatter by rank; 8 x 4B stores)
    float* knp = g_kn + (size_t)(o * INSZ + i) * 8;
#pragma unroll
    for (int k = 0; k < 8; k++) knp[rank[k]] = knee[k];

    // region tables. Region r = { v : exactly r knees are < v }.
    // a>0: s_k active iff v>knee (rank<r).  a<0: active iff v<knee (rank>=r).
    // a==0: s_k = relu(c_k) constant -> folds into B for all regions.
    float* outp = g_tab + (size_t)(o * INSZ + i) * 144;
#pragma unroll 1
    for (int r = 0; r < 9; r++) {
        float E[16];
#pragma unroll
        for (int j = 0; j < 8; j++) { E[j] = 0.0f; E[8 + j] = b2v[j]; }
#pragma unroll
        for (int k = 0; k < 8; k++) {
            bool act;
            float aa, cc;
            if (a[k] > 0.0f)      { act = (rank[k] < r);  }
            else if (a[k] < 0.0f) { act = (rank[k] >= r); }
            else                  { act = false; }
            aa = act ? a[k] : 0.0f;
            cc = act ? c[k] : 0.0f;
            if (a[k] == 0.0f && c[k] > 0.0f) cc = c[k];   // constant relu(c)
#pragma unroll
            for (int j = 0; j < 8; j++) {
                E[j]     += w2[j * 8 + k] * aa;
                E[8 + j] += w2[j * 8 + k] * cc;
            }
        }
#pragma unroll
        for (int q = 0; q < 4; q++)
            *(float4*)(outp + r * 16 + q * 4) = *(float4*)(E + q * 4);
    }
}

// ---------------------------------------------------------------------------
// Eval: block = (o, batch-chunk of 128); thread = input feature i.
// Per elem: region via 8 compares, 4x LDS128 of (A,B), 8 FFMA + 8 relu,
// packed layer-3 dot. Tables in dynamic smem (2 CTAs/SM).
// ---------------------------------------------------------------------------
__global__ void __launch_bounds__(128, 2)
mlpkan_eval(const float* __restrict__ x,
            const float* __restrict__ W3, const float* __restrict__ b3,
            float* __restrict__ out) {
    extern __shared__ float sm[];
    float* tab = sm;                             // [128][TSTRIDE]
    float* red = sm + INSZ * TSTRIDE;            // [32][129]
    float* pr  = red + 32 * 129;                 // [4][33]

    const int o     = blockIdx.x;
    const int chunk = blockIdx.y;
    const int i     = threadIdx.x;
    const int n     = i * OUTSZ + o;

    // x prefetch first (overlaps table load)
    const float* xp = x + (size_t)chunk * BC * INSZ + i;
    float vbuf[8];
#pragma unroll
    for (int p = 0; p < 8; p++) vbuf[p] = xp[(size_t)p * INSZ];

    // cooperative, fully-coalesced table load: 4608 float4s
    {
        const float4* gsrc = (const float4*)(g_tab + (size_t)o * (INSZ * 144));
#pragma unroll 1
        for (int f = i; f < 4608; f += 128) {
            float4 vv = gsrc[f];
            int row = f / 36, q = f - row * 36;
            *(float4*)(tab + row * TSTRIDE + q * 4) = vv;
        }
    }

    // per-thread knees + layer-3 weights
    float kn[8];
    {
        const float4* ks = (const float4*)(g_kn + (size_t)(o * INSZ + i) * 8);
        float4 k0 = ks[0], k1 = ks[1];
        kn[0] = k0.x; kn[1] = k0.y; kn[2] = k0.z; kn[3] = k0.w;
        kn[4] = k1.x; kn[5] = k1.y; kn[6] = k1.z; kn[7] = k1.w;
    }
    u64 w3p[4], b3p;
    {
        const float4* ws = (const float4*)(W3 + (size_t)n * 8);
        float4 wa = ws[0], wb = ws[1];
        w3p[0] = pk(wa.x, wa.y); w3p[1] = pk(wa.z, wa.w);
        w3p[2] = pk(wb.x, wb.y); w3p[3] = pk(wb.z, wb.w);
        b3p = pk(b3[n], 0.0f);
    }
    __syncthreads();                             // table visible to all

    const float* myTab = tab + i * TSTRIDE;

#pragma unroll 1
    for (int sub = 0; sub < 4; sub++) {
#pragma unroll 1
        for (int g = 0; g < 4; g++) {
#pragma unroll
            for (int u = 0; u < 8; u++) {
                const int b = sub * 32 + g * 8 + u;
                float v = vbuf[u];
                vbuf[u] = xp[(size_t)((b + 8) & 127) * INSZ];

                // region index: #knees strictly below v
                int r = (v > kn[0]) + (v > kn[1]) + (v > kn[2]) + (v > kn[3])
                      + (v > kn[4]) + (v > kn[5]) + (v > kn[6]) + (v > kn[7]);

                const float4* e = (const float4*)(myTab + r * 16);
                float4 A0 = e[0], A1 = e[1], B0 = e[2], B1 = e[3];

                float h0 = fmaxf(fmaf(A0.x, v, B0.x), 0.0f);
                float h1 = fmaxf(fmaf(A0.y, v, B0.y), 0.0f);
                float h2 = fmaxf(fmaf(A0.z, v, B0.z), 0.0f);
                float h3 = fmaxf(fmaf(A0.w, v, B0.w), 0.0f);
                float h4 = fmaxf(fmaf(A1.x, v, B1.x), 0.0f);
                float h5 = fmaxf(fmaf(A1.y, v, B1.y), 0.0f);
                float h6 = fmaxf(fmaf(A1.z, v, B1.z), 0.0f);
                float h7 = fmaxf(fmaf(A1.w, v, B1.w), 0.0f);

                u64 h01 = pk(h0, h1), h23 = pk(h2, h3);
                u64 h45 = pk(h4, h5), h67 = pk(h6, h7);
                u64 a0 = ffma2(w3p[0], h01, b3p);
                u64 a1 = fmul2(w3p[1], h23);
                a0 = ffma2(w3p[2], h45, a0);
                a1 = ffma2(w3p[3], h67, a1);
                u64 t = fadd2(a0, a1);
                float x0, x1; upk(t, x0, x1);

                red[(g * 8 + u) * 129 + i] = x0 + x1;
            }
        }
        __syncthreads();

        // spread reduction: thread (rb = i&31, rq = i>>5) sums 32 i-values
        {
            const int rb = i & 31, rq = i >> 5;
            const float* rr = &red[rb * 129 + rq * 32];
            float s0 = 0.f, s1 = 0.f, s2 = 0.f, s3 = 0.f;
#pragma unroll
            for (int cc = 0; cc < 32; cc += 4) {
                s0 += rr[cc + 0]; s1 += rr[cc + 1];
                s2 += rr[cc + 2]; s3 += rr[cc + 3];
            }
            pr[rq * 33 + rb] = (s0 + s1) + (s2 + s3);
        }
        __syncthreads();

        if (i < 32) {
            float r2 = (pr[i] + pr[33 + i]) + (pr[66 + i] + pr[99 + i]);
            out[(size_t)(chunk * BC + sub * 32 + i) * OUTSZ + o] = r2;
        }
    }
}

// ---------------------------------------------------------------------------
#define SMEM_BYTES ((INSZ * TSTRIDE + 32 * 129 + 4 * 33) * 4)

extern "C" void kernel_launch(void* const* d_in, const int* in_sizes, int n_in,
                              void* d_out, int out_size) {
    const float* x  = (const float*)d_in[0];
    const float* W1 = (const float*)d_in[1];
    const float* b1 = (const float*)d_in[2];
    const float* W2 = (const float*)d_in[3];
    const float* b2 = (const float*)d_in[4];
    const float* W3 = (const float*)d_in[5];
    const float* b3 = (const float*)d_in[6];
    float* out = (float*)d_out;

    cudaFuncSetAttribute(mlpkan_eval,
                         cudaFuncAttributeMaxDynamicSharedMemorySize, SMEM_BYTES);

    precompute_kernel<<<OUTSZ, INSZ>>>(W1, b1, W2, b2);
    mlpkan_eval<<<dim3(OUTSZ, NCHUNK), INSZ, SMEM_BYTES>>>(x, W3, b3, out);
}

// round 12
// speedup vs baseline: 2.1155x; 2.1155x over previous
#include <cuda_runtime.h>
#include <cstdint>
#include <cfloat>

#define INSZ   128
#define OUTSZ  128
#define BATCH  1024
#define NCHUNK 4
#define BC     (BATCH / NCHUNK)   // 256 elems per block

// smem layout (floats): tab 9*4*128*4 = 18432 | red 32*129 | pr 4*33
#define TABF   18432
#define SMEMF  (TABF + 32 * 129 + 4 * 33)

// ---------------------------------------------------------------------------
// Single fused kernel. Block = (o, chunk of 256 batch elems); thread = i.
// Phase 1 (per block): build the piecewise-affine layer-2 table for output o:
//   region r = #knees(v_k = -b1_k/W1_k) below v ; g_j(v) = A_j[r] v + B_j[r].
//   Stored bank-transposed: tab4[(r*4+q)*128 + i] -> lane-bank 4i, so the
//   r-divergent per-lane LDS.128 in phase 2 is conflict-free by construction.
// Phase 2: per elem: r via 8 compares, 4x LDS.128, 8 FMA + 8 relu, scalar dot.
// ---------------------------------------------------------------------------
__global__ void __launch_bounds__(128)
mlpkan_pw(const float* __restrict__ x,
          const float* __restrict__ W1, const float* __restrict__ b1,
          const float* __restrict__ W2, const float* __restrict__ b2,
          const float* __restrict__ W3, const float* __restrict__ b3,
          float* __restrict__ out) {
    extern __shared__ float sm[];
    float4* tab4 = (float4*)sm;            // [9][4][128] float4
    float*  red  = sm + TABF;              // [32][129]
    float*  pr   = red + 32 * 129;         // [4][33]

    const int o     = blockIdx.x;
    const int chunk = blockIdx.y;
    const int i     = threadIdx.x;
    const int n     = i * OUTSZ + o;
    const int g0    = (i >> 5) & 3;        // per-warp phase rotation

    // ---- x prefetch first (overlaps the table build) ----
    const float* xp = x + (size_t)chunk * BC * INSZ + i;
    float vbuf[8];
#pragma unroll
    for (int u = 0; u < 8; u++) vbuf[u] = xp[(size_t)(g0 * 8 + u) * INSZ];

    // ================= Phase 1: build table for subnet (i, o) ==============
    float a[8], c[8], w2[64], b2v[8];
    {
        const float4* W1v = (const float4*)(W1 + (size_t)n * 8);
        const float4* b1v = (const float4*)(b1 + (size_t)n * 8);
        float4 t0 = W1v[0], t1 = W1v[1];
        a[0]=t0.x; a[1]=t0.y; a[2]=t0.z; a[3]=t0.w;
        a[4]=t1.x; a[5]=t1.y; a[6]=t1.z; a[7]=t1.w;
        t0 = b1v[0]; t1 = b1v[1];
        c[0]=t0.x; c[1]=t0.y; c[2]=t0.z; c[3]=t0.w;
        c[4]=t1.x; c[5]=t1.y; c[6]=t1.z; c[7]=t1.w;
        const float4* W2v = (const float4*)(W2 + (size_t)n * 64);
#pragma unroll
        for (int q = 0; q < 16; q++) {
            float4 vv = W2v[q];
            w2[q*4+0]=vv.x; w2[q*4+1]=vv.y; w2[q*4+2]=vv.z; w2[q*4+3]=vv.w;
        }
        const float4* b2q = (const float4*)(b2 + (size_t)n * 8);
        t0 = b2q[0]; t1 = b2q[1];
        b2v[0]=t0.x; b2v[1]=t0.y; b2v[2]=t0.z; b2v[3]=t0.w;
        b2v[4]=t1.x; b2v[5]=t1.y; b2v[6]=t1.z; b2v[7]=t1.w;
    }

    // knees (a==0 -> -FLT_MAX sentinel: always counted; const term folds to B)
    float knee[8];
#pragma unroll
    for (int k = 0; k < 8; k++)
        knee[k] = (a[k] != 0.0f) ? (-c[k] / a[k]) : -FLT_MAX;

    // rank[k] = #knees strictly less (ties by index) — consistent with the
    // eval-side count r = sum(v > knee_k) over the same multiset.
    int rank[8];
#pragma unroll
    for (int k = 0; k < 8; k++) {
        int rk = 0;
#pragma unroll
        for (int m = 0; m < 8; m++)
            rk += (knee[m] < knee[k]) || (knee[m] == knee[k] && m < k);
        rank[k] = rk;
    }

    // region tables -> smem, bank-transposed
#pragma unroll 1
    for (int r = 0; r < 9; r++) {
        float E[16];
#pragma unroll
        for (int j = 0; j < 8; j++) { E[j] = 0.0f; E[8 + j] = b2v[j]; }
#pragma unroll
        for (int k = 0; k < 8; k++) {
            bool act;
            if (a[k] > 0.0f)      act = (rank[k] < r);
            else if (a[k] < 0.0f) act = (rank[k] >= r);
            else                  act = false;
            float aa = act ? a[k] : 0.0f;
            float cc = act ? c[k] : 0.0f;
            if (a[k] == 0.0f && c[k] > 0.0f) cc = c[k];   // constant relu(c)
#pragma unroll
            for (int j = 0; j < 8; j++) {
                E[j]     += w2[j * 8 + k] * aa;
                E[8 + j] += w2[j * 8 + k] * cc;
            }
        }
#pragma unroll
        for (int q = 0; q < 4; q++)
            tab4[(r * 4 + q) * 128 + i] = *(float4*)(E + q * 4);
    }

    // layer-3 weights
    float w3[8], b3v;
    {
        const float4* ws = (const float4*)(W3 + (size_t)n * 8);
        float4 wa = ws[0], wb = ws[1];
        w3[0]=wa.x; w3[1]=wa.y; w3[2]=wa.z; w3[3]=wa.w;
        w3[4]=wb.x; w3[5]=wb.y; w3[6]=wb.z; w3[7]=wb.w;
        b3v = b3[n];
    }
    __syncthreads();                        // table visible to all warps

    // ===================== Phase 2: eval 256 elems =========================
#pragma unroll 1
    for (int s = 0; s < 8; s++) {           // 8 supersteps of 32 elems
#pragma unroll 1
        for (int t = 0; t < 4; t++) {
            const int gg = (g0 + t) & 3;
            const int gn = (g0 + t + 1) & 3;
            const int nbase = (t < 3) ? (s * 32 + gn * 8)
                                      : (((s + 1) & 7) * 32 + g0 * 8);
#pragma unroll
            for (int u = 0; u < 8; u++) {
                const int bb = gg * 8 + u;         // elem within superstep
                float v = vbuf[u];
                vbuf[u] = xp[(size_t)(nbase + u) * INSZ];

                // region: count of knees below v (sort-free)
                int r = (v > knee[0]) + (v > knee[1]) + (v > knee[2]) + (v > knee[3])
                      + (v > knee[4]) + (v > knee[5]) + (v > knee[6]) + (v > knee[7]);

                const int base = r * 4 * 128 + i;
                float4 A0 = tab4[base];
                float4 A1 = tab4[base + 128];
                float4 B0 = tab4[base + 256];
                float4 B1 = tab4[base + 384];

                float h0 = fmaxf(fmaf(A0.x, v, B0.x), 0.0f);
                float h1 = fmaxf(fmaf(A0.y, v, B0.y), 0.0f);
                float h2 = fmaxf(fmaf(A0.z, v, B0.z), 0.0f);
                float h3 = fmaxf(fmaf(A0.w, v, B0.w), 0.0f);
                float h4 = fmaxf(fmaf(A1.x, v, B1.x), 0.0f);
                float h5 = fmaxf(fmaf(A1.y, v, B1.y), 0.0f);
                float h6 = fmaxf(fmaf(A1.z, v, B1.z), 0.0f);
                float h7 = fmaxf(fmaf(A1.w, v, B1.w), 0.0f);

                // scalar layer-3 dot, two chains
                float y0 = fmaf(w3[0], h0, b3v);
                float y1 = w3[1] * h1;
                y0 = fmaf(w3[2], h2, y0);  y1 = fmaf(w3[3], h3, y1);
                y0 = fmaf(w3[4], h4, y0);  y1 = fmaf(w3[5], h5, y1);
                y0 = fmaf(w3[6], h6, y0);  y1 = fmaf(w3[7], h7, y1);

                red[bb * 129 + i] = y0 + y1;
            }
        }
        __syncthreads();

        // stage-1 reduction: thread (rb = i&31, rq = i>>5) sums 32 i-values
        {
            const int rb = i & 31, rq = i >> 5;
            const float* rr = &red[rb * 129 + rq * 32];
            float s0 = 0.f, s1 = 0.f, s2 = 0.f, s3 = 0.f;
#pragma unroll
            for (int cc = 0; cc < 32; cc += 4) {
                s0 += rr[cc + 0]; s1 += rr[cc + 1];
                s2 += rr[cc + 2]; s3 += rr[cc + 3];
            }
            pr[rq * 33 + rb] = (s0 + s1) + (s2 + s3);
        }
        __syncthreads();

        // stage-2: combine + store (overlaps next superstep's compute)
        if (i < 32) {
            float rv = (pr[i] + pr[33 + i]) + (pr[66 + i] + pr[99 + i]);
            out[(size_t)(chunk * BC + s * 32 + i) * OUTSZ + o] = rv;
        }
    }
}

// ---------------------------------------------------------------------------
extern "C" void kernel_launch(void* const* d_in, const int* in_sizes, int n_in,
                              void* d_out, int out_size) {
    const float* x  = (const float*)d_in[0];
    const float* W1 = (const float*)d_in[1];
    const float* b1 = (const float*)d_in[2];
    const float* W2 = (const float*)d_in[3];
    const float* b2 = (const float*)d_in[4];
    const float* W3 = (const float*)d_in[5];
    const float* b3 = (const float*)d_in[6];
    float* out = (float*)d_out;

    static int configured = 0;
    if (!configured) {   // idempotent attribute set (host-side, no alloc)
        cudaFuncSetAttribute(mlpkan_pw,
                             cudaFuncAttributeMaxDynamicSharedMemorySize,
                             SMEMF * 4);
        configured = 1;
    }

    mlpkan_pw<<<dim3(OUTSZ, NCHUNK), INSZ, SMEMF * 4>>>(
        x, W1, b1, W2, b2, W3, b3, out);
}

// round 13
// speedup vs baseline: 2.8665x; 1.3550x over previous
#include <cuda_runtime.h>
#include <cstdint>
#include <cfloat>

#define INSZ   128
#define OUTSZ  128
#define BATCH  1024
#define GB     256            // batch elems per group
#define TABF   18432          // 9*4*128 float4 = floats
#define REDF   (4 * 8 * 129)  // per-group red [8][129]
#define PRF    (4 * 16 * 9)   // per-group pr  [16][9]
#define SMEMF  (TABF + REDF + PRF)

typedef unsigned long long u64;

// ---------------------------------------------------------------------------
// One 512-thread CTA per output o. Groups g=0..3 (128 threads each, thread =
// input feature i) evaluate disjoint 256-elem batch ranges against ONE shared
// piecewise-affine table:
//   region r(v) = #knees below v,  knee_k = -b1_k/W1_k
//   g_j(v) = A_j[r]*v + B_j[r]  (exact algebra -> matches direct eval)
// Table bank-transposed [r][q][i] so per-lane r-divergent LDS.128 is
// conflict-free. Group-local named barriers; no cross-group phase locking.
// ---------------------------------------------------------------------------
__global__ void __launch_bounds__(512)
mlpkan_pw(const float* __restrict__ x,
          const float* __restrict__ W1, const float* __restrict__ b1,
          const float* __restrict__ W2, const float* __restrict__ b2,
          const float* __restrict__ W3, const float* __restrict__ b3,
          float* __restrict__ out) {
    extern __shared__ float sm[];
    float4* tab4 = (float4*)sm;                 // [9][4][128] float4
    float*  redA = sm + TABF;                   // [4][8][129]
    float*  prA  = redA + REDF;                 // [4][16][9]

    const int o   = blockIdx.x;
    const int tid = threadIdx.x;
    const int g   = tid >> 7;                   // batch group 0..3
    const int i   = tid & 127;                  // input feature
    const int n   = i * OUTSZ + o;              // subnet id
    const int w4  = (tid >> 5) & 3;             // warp within group

    float* red = redA + g * (8 * 129);
    float* pr  = prA  + g * (16 * 9);

    // elem-slot rotation within each 8-elem superstep (per-warp de-phasing)
    int e[8];
#pragma unroll
    for (int u = 0; u < 8; u++) e[u] = (u + 2 * w4) & 7;

    // ---- x prefetch for this group's first superstep ----
    const float* xp = x + (size_t)g * GB * INSZ + i;
    float vbuf[8];
#pragma unroll
    for (int u = 0; u < 8; u++) vbuf[u] = xp[(size_t)e[u] * INSZ];

    // ============== build: knees/ranks (all threads, redundant per group) ===
    float a[8], c[8], b2v[8];
    {
        const float4* W1v = (const float4*)(W1 + (size_t)n * 8);
        const float4* b1v = (const float4*)(b1 + (size_t)n * 8);
        float4 t0 = W1v[0], t1 = W1v[1];
        a[0]=t0.x; a[1]=t0.y; a[2]=t0.z; a[3]=t0.w;
        a[4]=t1.x; a[5]=t1.y; a[6]=t1.z; a[7]=t1.w;
        t0 = b1v[0]; t1 = b1v[1];
        c[0]=t0.x; c[1]=t0.y; c[2]=t0.z; c[3]=t0.w;
        c[4]=t1.x; c[5]=t1.y; c[6]=t1.z; c[7]=t1.w;
        const float4* b2q = (const float4*)(b2 + (size_t)n * 8);
        t0 = b2q[0]; t1 = b2q[1];
        b2v[0]=t0.x; b2v[1]=t0.y; b2v[2]=t0.z; b2v[3]=t0.w;
        b2v[4]=t1.x; b2v[5]=t1.y; b2v[6]=t1.z; b2v[7]=t1.w;
    }

    float knee[8];
#pragma unroll
    for (int k = 0; k < 8; k++)
        knee[k] = (a[k] != 0.0f) ? (-c[k] / a[k]) : -FLT_MAX;

    int rank[8];
#pragma unroll
    for (int k = 0; k < 8; k++) {
        int rk = 0;
#pragma unroll
        for (int m = 0; m < 8; m++)
            rk += (knee[m] < knee[k]) || (knee[m] == knee[k] && m < k);
        rank[k] = rk;
    }

    // ====== build: regions r = g, g+4, g+8 (split across groups) ===========
#pragma unroll 1
    for (int r = g; r < 9; r += 4) {
        float aa[8], cc[8];
#pragma unroll
        for (int k = 0; k < 8; k++) {
            bool act;
            if (a[k] > 0.0f)      act = (rank[k] < r);
            else if (a[k] < 0.0f) act = (rank[k] >= r);
            else                  act = false;
            aa[k] = act ? a[k] : 0.0f;
            cc[k] = act ? c[k] : 0.0f;
            if (a[k] == 0.0f && c[k] > 0.0f) cc[k] = c[k];  // const relu(c)
        }
        float E[16];
        const float4* W2v = (const float4*)(W2 + (size_t)n * 64);
#pragma unroll
        for (int j = 0; j < 8; j++) {
            float4 r0 = W2v[2 * j], r1 = W2v[2 * j + 1];
            float w2r[8] = {r0.x, r0.y, r0.z, r0.w, r1.x, r1.y, r1.z, r1.w};
            float sA = 0.0f, sB = b2v[j];
#pragma unroll
            for (int k = 0; k < 8; k++) {
                sA = fmaf(w2r[k], aa[k], sA);
                sB = fmaf(w2r[k], cc[k], sB);
            }
            E[j] = sA; E[8 + j] = sB;
        }
#pragma unroll
        for (int q = 0; q < 4; q++)
            tab4[(r * 4 + q) * 128 + i] = *(float4*)(E + q * 4);
    }

    // layer-3 weights
    float w3[8], b3v;
    {
        const float4* ws = (const float4*)(W3 + (size_t)n * 8);
        float4 wa = ws[0], wb = ws[1];
        w3[0]=wa.x; w3[1]=wa.y; w3[2]=wa.z; w3[3]=wa.w;
        w3[4]=wb.x; w3[5]=wb.y; w3[6]=wb.z; w3[7]=wb.w;
        b3v = b3[n];
    }
    __syncthreads();                            // whole table visible

    // ================= eval: 32 supersteps of 8 elems per group =============
#pragma unroll 1
    for (int s = 0; s < 32; s++) {
#pragma unroll
        for (int u = 0; u < 8; u++) {
            const int bb = e[u];                // row within superstep
            const int b  = s * 8 + bb;          // elem within group range
            float v = vbuf[u];
            vbuf[u] = xp[(size_t)((b + 8) & 255) * INSZ];   // wrap prefetch

            int r = (v > knee[0]) + (v > knee[1]) + (v > knee[2]) + (v > knee[3])
                  + (v > knee[4]) + (v > knee[5]) + (v > knee[6]) + (v > knee[7]);

            const int base = r * 4 * 128 + i;
            float4 A0 = tab4[base];
            float4 A1 = tab4[base + 128];
            float4 B0 = tab4[base + 256];
            float4 B1 = tab4[base + 384];

            float h0 = fmaxf(fmaf(A0.x, v, B0.x), 0.0f);
            float h1 = fmaxf(fmaf(A0.y, v, B0.y), 0.0f);
            float h2 = fmaxf(fmaf(A0.z, v, B0.z), 0.0f);
            float h3 = fmaxf(fmaf(A0.w, v, B0.w), 0.0f);
            float h4 = fmaxf(fmaf(A1.x, v, B1.x), 0.0f);
            float h5 = fmaxf(fmaf(A1.y, v, B1.y), 0.0f);
            float h6 = fmaxf(fmaf(A1.z, v, B1.z), 0.0f);
            float h7 = fmaxf(fmaf(A1.w, v, B1.w), 0.0f);

            float y0 = fmaf(w3[0], h0, b3v);
            float y1 = w3[1] * h1;
            y0 = fmaf(w3[2], h2, y0);  y1 = fmaf(w3[3], h3, y1);
            y0 = fmaf(w3[4], h4, y0);  y1 = fmaf(w3[5], h5, y1);
            y0 = fmaf(w3[6], h6, y0);  y1 = fmaf(w3[7], h7, y1);

            red[bb * 129 + i] = y0 + y1;
        }
        asm volatile("bar.sync %0, %1;" :: "r"(g + 1), "r"(128) : "memory");

        // stage-1: thread (bb = i&7, rq = i>>3) sums 8 i-values of row bb
        {
            const int bb = i & 7, rq = i >> 3;
            const float* rr = &red[bb * 129 + rq * 8];
            float s0 = rr[0] + rr[1], s1 = rr[2] + rr[3];
            float s2 = rr[4] + rr[5], s3 = rr[6] + rr[7];
            pr[rq * 9 + bb] = (s0 + s1) + (s2 + s3);
        }
        asm volatile("bar.sync %0, %1;" :: "r"(g + 1), "r"(128) : "memory");

        // stage-2: 8 lanes combine 16 partials + store (overlaps next eval)
        if (i < 8) {
            float r0 = 0.f, r1 = 0.f;
#pragma unroll
            for (int q = 0; q < 16; q += 2) {
                r0 += pr[q * 9 + i];
                r1 += pr[(q + 1) * 9 + i];
            }
            out[(size_t)(g * GB + s * 8 + i) * OUTSZ + o] = r0 + r1;
        }
    }
}

// ---------------------------------------------------------------------------
extern "C" void kernel_launch(void* const* d_in, const int* in_sizes, int n_in,
                              void* d_out, int out_size) {
    const float* x  = (const float*)d_in[0];
    const float* W1 = (const float*)d_in[1];
    const float* b1 = (const float*)d_in[2];
    const float* W2 = (const float*)d_in[3];
    const float* b2 = (const float*)d_in[4];
    const float* W3 = (const float*)d_in[5];
    const float* b3 = (const float*)d_in[6];
    float* out = (float*)d_out;

    static int configured = 0;
    if (!configured) {
        cudaFuncSetAttribute(mlpkan_pw,
                             cudaFuncAttributeMaxDynamicSharedMemorySize,
                             SMEMF * 4);
        configured = 1;
    }

    mlpkan_pw<<<OUTSZ, 512, SMEMF * 4>>>(x, W1, b1, W2, b2, W3, b3, out);
}